// round 13
// baseline (speedup 1.0000x reference)
#include <cuda_runtime.h>
#include <cuda_bf16.h>
#include <cstdint>

// ===========================================================================
// MainModelAttention via legacy tensor cores (mma.sync bf16, plain sm_80 PTX).
// context = softmax((X Wq^T + bq)(X Wk^T + bk)^T / sqrt(128) + mask)(X Wv^T+bv)
// B=2, S=4096, H=2048, fp32 I/O.
//
// Precision: fp32 x = hi + lo (bf16 each), rows stored [hi(0..K-1)|lo(K..2K-1)].
// GEMM accumulates hi*hi + hi*lo + lo*hi in fp32 -> ~2^-18 product error.
//
// R13 (= R12 re-land; R12 failed on infra "device busy" before any run):
// cp.async issue moved off the wait critical path (stage_loads issued after
// kh0 fragments, overlapping MMA; top-of-loop wait is WAIT0) + V
// transpose/hi-lo split fused into the V-GEMM epilogue (emode 3).
// ===========================================================================

#define BATCH 2
#define SEQ   4096
#define HID   2048
#define MROWS (BATCH*SEQ)   // 8192
#define KX    (2*HID)
#define KPV   (2*SEQ)

// ---- scratch (__device__ globals; allocation-free) ----
__device__ __align__(256) __nv_bfloat16 g_Xhl[(size_t)MROWS * KX];
__device__ __align__(256) __nv_bfloat16 g_Whl[3][(size_t)HID * KX];
__device__ __align__(256) __nv_bfloat16 g_Qhl[(size_t)MROWS * KX];
__device__ __align__(256) __nv_bfloat16 g_Khl[(size_t)MROWS * KX];
__device__ __align__(256) __nv_bfloat16 g_Vthl[(size_t)BATCH * HID * KPV];
__device__ __align__(256) float         g_Sf[(size_t)BATCH * SEQ * SEQ];
__device__ __align__(256) __nv_bfloat16 g_Phl[(size_t)BATCH * SEQ * KPV];

enum { SEL_XHL = 0, SEL_WQ, SEL_WK, SEL_WV, SEL_QHL, SEL_KHL, SEL_VTHL, SEL_PHL };
enum { FSEL_SF = 0 };

__device__ __forceinline__ __nv_bfloat16* bselw(int s) {
    switch (s) {
        case SEL_XHL:  return g_Xhl;
        case SEL_WQ:   return g_Whl[0];
        case SEL_WK:   return g_Whl[1];
        case SEL_WV:   return g_Whl[2];
        case SEL_QHL:  return g_Qhl;
        case SEL_KHL:  return g_Khl;
        case SEL_VTHL: return g_Vthl;
        default:       return g_Phl;
    }
}
__device__ __forceinline__ float* fselw(int s, float* ext) {
    switch (s) {
        case FSEL_SF: return g_Sf;
        default:      return ext;
    }
}

// ---- PTX helpers ----
__device__ __forceinline__ uint32_t smem_to_u32(const void* p) {
    uint32_t a;
    asm("{ .reg .u64 t; cvta.to.shared.u64 t, %1; cvt.u32.u64 %0, t; }"
        : "=r"(a) : "l"(p));
    return a;
}
#define CP_ASYNC16(dst, src) \
    asm volatile("cp.async.cg.shared.global [%0], [%1], 16;" :: "r"(dst), "l"(src))
#define CP_COMMIT() asm volatile("cp.async.commit_group;" ::: "memory")
#define CP_WAIT0()  asm volatile("cp.async.wait_group 0;" ::: "memory")

__device__ __forceinline__ void ldsm4(uint32_t r[4], uint32_t a) {
    asm volatile("ldmatrix.sync.aligned.m8n8.x4.shared.b16 {%0,%1,%2,%3}, [%4];"
                 : "=r"(r[0]), "=r"(r[1]), "=r"(r[2]), "=r"(r[3]) : "r"(a));
}
__device__ __forceinline__ void mma_bf16(float d[4], const uint32_t a[4],
                                         const uint32_t b0, const uint32_t b1) {
    asm volatile(
        "mma.sync.aligned.m16n8k16.row.col.f32.bf16.bf16.f32 "
        "{%0,%1,%2,%3}, {%4,%5,%6,%7}, {%8,%9}, {%0,%1,%2,%3};"
        : "+f"(d[0]), "+f"(d[1]), "+f"(d[2]), "+f"(d[3])
        : "r"(a[0]), "r"(a[1]), "r"(a[2]), "r"(a[3]), "r"(b0), "r"(b1));
}

__device__ __forceinline__ uint32_t pack_hi(float a, float b, uint32_t& lo) {
    __nv_bfloat16 ha = __float2bfloat16(a);
    __nv_bfloat16 hb = __float2bfloat16(b);
    __nv_bfloat162 l;
    l.x = __float2bfloat16(a - __bfloat162float(ha));
    l.y = __float2bfloat16(b - __bfloat162float(hb));
    lo = *reinterpret_cast<uint32_t*>(&l);
    __nv_bfloat162 h; h.x = ha; h.y = hb;
    return *reinterpret_cast<uint32_t*>(&h);
}
__device__ __forceinline__ void split1(float x, __nv_bfloat16& h, __nv_bfloat16& l) {
    h = __float2bfloat16(x);
    l = __float2bfloat16(x - __bfloat162float(h));
}

// ===========================================================================
// GEMM-NT bf16 hi/lo (HMMA): C[m,n] = sum_k (Ahi+Alo)[m,k]*(Bhi+Blo)[n,k]
// Tile 128x128, BK=64, 8 warps (2x4) of 64x32 warp tiles.
// 3-stage cp.async ring, one __syncthreads per chunk; next-chunk cp.async is
// issued AFTER the kh0 fragment loads so LDGSTS issue overlaps MMA issue and
// the top-of-loop wait is WAIT0 (only the current chunk's group in flight).
// ROWB=144: 144/16=9 (odd) -> 8 consecutive rows hit 8 distinct 16B banks.
// Epilogue modes: 0 = fp32 (+bias); 1 = bf16 hi/lo into bselw(Csel);
//                 2 = fp32 * scale + mask[z*N + col];
//                 3 = bf16 hi/lo TRANSPOSED into g_Vthl (+bias).
// ===========================================================================
#define ROWB    144
#define TILE_B  (128 * ROWB)           // 18432
#define STAGE_B (4 * TILE_B)           // 73728 (Ahi,Alo,Bhi,Blo)
#define NSTAGE  3
#define GEMM_SMEM (NSTAGE * STAGE_B)   // 221184

__device__ __forceinline__ void stage_loads(
    uint32_t smStage, const __nv_bfloat16* Ahi, const __nv_bfloat16* Alo,
    const __nv_bfloat16* Bhi, const __nv_bfloat16* Blo, size_t ld, int tid)
{
#pragma unroll
    for (int j = 0; j < 4; j++) {
        const int within = j * 256 + tid;      // 0..1023
        const int r = within >> 3, c = within & 7;
        const size_t go = (size_t)r * ld + c * 8;
        const uint32_t so = (uint32_t)(r * ROWB + c * 16);
        CP_ASYNC16(smStage + 0 * TILE_B + so, Ahi + go);
        CP_ASYNC16(smStage + 1 * TILE_B + so, Alo + go);
        CP_ASYNC16(smStage + 2 * TILE_B + so, Bhi + go);
        CP_ASYNC16(smStage + 3 * TILE_B + so, Blo + go);
    }
}

__global__ void __launch_bounds__(256)
gemm_hmma(int Asel, int Bsel, const float* __restrict__ bias,
          int emode, int Csel, float* __restrict__ Cext,
          const float* __restrict__ mask, float scale,
          int Korig, int N, size_t sA, size_t sB, size_t sC)
{
    extern __shared__ __align__(16) char sm[];
    const uint32_t smb = smem_to_u32(sm);
    const int tid = threadIdx.x;
    const int lane = tid & 31, warp = tid >> 5;
    const size_t ld = (size_t)2 * Korig;

    const __nv_bfloat16* A = bselw(Asel) + blockIdx.z * sA + (size_t)blockIdx.y * 128 * ld;
    const __nv_bfloat16* B = bselw(Bsel) + blockIdx.z * sB + (size_t)blockIdx.x * 128 * ld;

    const int m0 = (warp >> 2) * 64;     // warp tile origin
    const int n0 = (warp & 3) * 32;

    const uint32_t aLane = (uint32_t)((m0 + (lane & 15)) * ROWB + ((lane >> 4) << 4));
    const uint32_t bLane = (uint32_t)((n0 + ((lane >> 4) << 3) + (lane & 7)) * ROWB
                                      + (((lane >> 3) & 1) << 4));

    float acc[4][4][4];
#pragma unroll
    for (int i = 0; i < 4; i++)
#pragma unroll
        for (int j = 0; j < 4; j++)
#pragma unroll
            for (int q = 0; q < 4; q++) acc[i][j][q] = 0.f;

    // Double-buffered register fragments (kh software pipeline).
    uint32_t ah[2][4][4], al[2][4][4], bh[2][2][4], bl[2][2][4];

    const int T = Korig / 64;
    stage_loads(smb, A, A + Korig, B, B + Korig, ld, tid);
    CP_COMMIT();

    int stageIdx = 0;       // ring slot of chunk t
    for (int t = 0; t < T; t++) {
        CP_WAIT0();          // only chunk t's group is in flight here
        __syncthreads();     // 3-stage ring: write slot of the upcoming
                             // prefetch is two barriers from its last reader

        const uint32_t stage = smb + stageIdx * STAGE_B;
        const uint32_t aBase = stage + aLane;
        const uint32_t bBase = stage + 2 * TILE_B + bLane;

        // kh0 fragments first, so MMAs can start immediately...
#pragma unroll
        for (int mt = 0; mt < 4; mt++) {
            ldsm4(ah[0][mt], aBase + mt * (16 * ROWB));
            ldsm4(al[0][mt], aBase + mt * (16 * ROWB) + TILE_B);
        }
#pragma unroll
        for (int nt = 0; nt < 2; nt++) {
            ldsm4(bh[0][nt], bBase + nt * (16 * ROWB));
            ldsm4(bl[0][nt], bBase + nt * (16 * ROWB) + TILE_B);
        }

        // ...then issue next chunk's cp.async, overlapping the MMA stream.
        if (t + 1 < T) {
            const int kt = (t + 1) * 64;
            const int nslot = (stageIdx + 1 == NSTAGE) ? 0 : stageIdx + 1;
            stage_loads(smb + nslot * STAGE_B,
                        A + kt, A + Korig + kt, B + kt, B + Korig + kt, ld, tid);
            CP_COMMIT();
        }

#pragma unroll
        for (int kh = 0; kh < 4; kh++) {
            const int cur = kh & 1, nxt = cur ^ 1;
            if (kh < 3) {
                const uint32_t aN = aBase + (kh + 1) * 32;
                const uint32_t bN = bBase + (kh + 1) * 32;
#pragma unroll
                for (int mt = 0; mt < 4; mt++) {
                    ldsm4(ah[nxt][mt], aN + mt * (16 * ROWB));
                    ldsm4(al[nxt][mt], aN + mt * (16 * ROWB) + TILE_B);
                }
#pragma unroll
                for (int nt = 0; nt < 2; nt++) {
                    ldsm4(bh[nxt][nt], bN + nt * (16 * ROWB));
                    ldsm4(bl[nxt][nt], bN + nt * (16 * ROWB) + TILE_B);
                }
            }
            // pass 1: hi*hi
#pragma unroll
            for (int mt = 0; mt < 4; mt++)
#pragma unroll
                for (int n8 = 0; n8 < 4; n8++)
                    mma_bf16(acc[mt][n8], ah[cur][mt],
                             bh[cur][n8 >> 1][(n8 & 1) * 2],
                             bh[cur][n8 >> 1][(n8 & 1) * 2 + 1]);
            // pass 2: hi*lo
#pragma unroll
            for (int mt = 0; mt < 4; mt++)
#pragma unroll
                for (int n8 = 0; n8 < 4; n8++)
                    mma_bf16(acc[mt][n8], ah[cur][mt],
                             bl[cur][n8 >> 1][(n8 & 1) * 2],
                             bl[cur][n8 >> 1][(n8 & 1) * 2 + 1]);
            // pass 3: lo*hi
#pragma unroll
            for (int mt = 0; mt < 4; mt++)
#pragma unroll
                for (int n8 = 0; n8 < 4; n8++)
                    mma_bf16(acc[mt][n8], al[cur][mt],
                             bh[cur][n8 >> 1][(n8 & 1) * 2],
                             bh[cur][n8 >> 1][(n8 & 1) * 2 + 1]);
        }
        stageIdx = (stageIdx + 1 == NSTAGE) ? 0 : stageIdx + 1;
    }

    // Epilogue. Fragment: c0,c1 = (row g, col 2t / 2t+1); c2,c3 = row g+8.
    const int g = lane >> 2, tq = lane & 3;
    if (emode == 1) {
        // bf16 hi/lo output rows of width 2N: [hi | lo]
        __nv_bfloat16* O = bselw(Csel) + blockIdx.z * sC;
        const size_t W2 = (size_t)2 * N;
#pragma unroll
        for (int mt = 0; mt < 4; mt++) {
            const size_t r0 = (size_t)blockIdx.y * 128 + m0 + mt * 16 + g;
#pragma unroll
            for (int n8 = 0; n8 < 4; n8++) {
                const size_t col = (size_t)blockIdx.x * 128 + n0 + n8 * 8 + 2 * tq;
                float b0 = 0.f, b1 = 0.f;
                if (bias) { b0 = bias[col]; b1 = bias[col + 1]; }
                uint32_t lo0, lo1;
                const uint32_t h0 = pack_hi(acc[mt][n8][0] + b0, acc[mt][n8][1] + b1, lo0);
                const uint32_t h1 = pack_hi(acc[mt][n8][2] + b0, acc[mt][n8][3] + b1, lo1);
                *(uint32_t*)(O + r0 * W2 + col)             = h0;
                *(uint32_t*)(O + r0 * W2 + N + col)         = lo0;
                *(uint32_t*)(O + (r0 + 8) * W2 + col)       = h1;
                *(uint32_t*)(O + (r0 + 8) * W2 + N + col)   = lo1;
            }
        }
    } else if (emode == 3) {
        // V: write transposed bf16 hi/lo into g_Vthl[b][h][ hi(s) | lo(s) ].
        // Output element (row=s_global, col=h): Vthl[b][h][s], b=row>>12.
#pragma unroll
        for (int mt = 0; mt < 4; mt++) {
            const int r0 = (int)(blockIdx.y * 128 + m0 + mt * 16 + g);
            const int b = r0 >> 12;            // SEQ = 4096
            const int s = r0 & (SEQ - 1);      // tile never straddles batches
            __nv_bfloat16* Ob = g_Vthl + (size_t)b * HID * KPV;
#pragma unroll
            for (int n8 = 0; n8 < 4; n8++) {
                const int col = (int)(blockIdx.x * 128 + n0 + n8 * 8 + 2 * tq);
                const float b0 = bias[col], b1 = bias[col + 1];
                __nv_bfloat16* c0p = Ob + (size_t)col * KPV;
                __nv_bfloat16* c1p = Ob + (size_t)(col + 1) * KPV;
                __nv_bfloat16 h, l;
                split1(acc[mt][n8][0] + b0, h, l);  c0p[s] = h;       c0p[SEQ + s] = l;
                split1(acc[mt][n8][1] + b1, h, l);  c1p[s] = h;       c1p[SEQ + s] = l;
                split1(acc[mt][n8][2] + b0, h, l);  c0p[s + 8] = h;   c0p[SEQ + s + 8] = l;
                split1(acc[mt][n8][3] + b1, h, l);  c1p[s + 8] = h;   c1p[SEQ + s + 8] = l;
            }
        }
    } else {
        float* C = fselw(Csel, Cext) + blockIdx.z * sC;
#pragma unroll
        for (int mt = 0; mt < 4; mt++) {
            const size_t r0 = (size_t)blockIdx.y * 128 + m0 + mt * 16 + g;
#pragma unroll
            for (int n8 = 0; n8 < 4; n8++) {
                const size_t col = (size_t)blockIdx.x * 128 + n0 + n8 * 8 + 2 * tq;
                float b0 = 0.f, b1 = 0.f;
                if (emode == 2) {
                    b0 = mask[(size_t)blockIdx.z * N + col];
                    b1 = mask[(size_t)blockIdx.z * N + col + 1];
                } else if (bias) {
                    b0 = bias[col]; b1 = bias[col + 1];
                }
                const float s = (emode == 2) ? scale : 1.f;
                float2 v0 = { acc[mt][n8][0] * s + b0, acc[mt][n8][1] * s + b1 };
                float2 v1 = { acc[mt][n8][2] * s + b0, acc[mt][n8][3] * s + b1 };
                *(float2*)(C + r0 * N + col) = v0;
                *(float2*)(C + (r0 + 8) * N + col) = v1;
            }
        }
    }
}

// ===========================================================================
// fp32 -> bf16 hi/lo convert, 8 elements/thread (vectorized).
// ===========================================================================
__global__ void __launch_bounds__(256)
cvt_hilo8(const float* __restrict__ in, int outSel, int C, size_t n)
{
    const size_t i = ((size_t)blockIdx.x * 256 + threadIdx.x) * 8;
    if (i >= n) return;
    __nv_bfloat16* out = bselw(outSel);
    const size_t r = i / (size_t)C, c = i - r * (size_t)C;

    float4 v0 = *(const float4*)(in + i);
    float4 v1 = *(const float4*)(in + i + 4);
    uint32_t h[4], l[4];
    h[0] = pack_hi(v0.x, v0.y, l[0]);
    h[1] = pack_hi(v0.z, v0.w, l[1]);
    h[2] = pack_hi(v1.x, v1.y, l[2]);
    h[3] = pack_hi(v1.z, v1.w, l[3]);
    __nv_bfloat16* oh = out + r * (size_t)(2 * C) + c;
    *(uint4*)oh       = *(uint4*)h;
    *(uint4*)(oh + C) = *(uint4*)l;
}

// ===========================================================================
// Row softmax over pre-scaled+masked scores: P = softmax(S) as bf16 hi/lo.
// ===========================================================================
__global__ void __launch_bounds__(256)
softmax_rows()
{
    __shared__ float buf[SEQ];
    __shared__ float red[8];

    const int row = blockIdx.x;
    const float* srow = g_Sf + (size_t)row * SEQ;
    __nv_bfloat16* prow = g_Phl + (size_t)row * KPV;
    const int tid = threadIdx.x;

    float lmax = -3.4028235e38f;
    for (int i = tid * 4; i < SEQ; i += 256 * 4) {
        float4 v = *(const float4*)(srow + i);
        *(float4*)&buf[i] = v;
        lmax = fmaxf(lmax, fmaxf(fmaxf(v.x, v.y), fmaxf(v.z, v.w)));
    }
#pragma unroll
    for (int o = 16; o; o >>= 1)
        lmax = fmaxf(lmax, __shfl_xor_sync(0xffffffffu, lmax, o));
    if ((tid & 31) == 0) red[tid >> 5] = lmax;
    __syncthreads();
    if (tid < 32) {
        float v = (tid < 8) ? red[tid] : -3.4028235e38f;
#pragma unroll
        for (int o = 4; o; o >>= 1)
            v = fmaxf(v, __shfl_xor_sync(0xffffffffu, v, o));
        if (tid == 0) red[0] = v;
    }
    __syncthreads();
    const float bmax = red[0];
    __syncthreads();

    float lsum = 0.f;
    for (int i = tid * 4; i < SEQ; i += 256 * 4) {
        float4 v = *(float4*)&buf[i];
        v.x = __expf(v.x - bmax); v.y = __expf(v.y - bmax);
        v.z = __expf(v.z - bmax); v.w = __expf(v.w - bmax);
        *(float4*)&buf[i] = v;
        lsum += v.x + v.y + v.z + v.w;
    }
#pragma unroll
    for (int o = 16; o; o >>= 1)
        lsum += __shfl_xor_sync(0xffffffffu, lsum, o);
    if ((tid & 31) == 0) red[tid >> 5] = lsum;
    __syncthreads();
    if (tid < 32) {
        float v = (tid < 8) ? red[tid] : 0.f;
#pragma unroll
        for (int o = 4; o; o >>= 1)
            v += __shfl_xor_sync(0xffffffffu, v, o);
        if (tid == 0) red[0] = v;
    }
    __syncthreads();
    const float inv = 1.f / red[0];

    for (int i = tid * 4; i < SEQ; i += 256 * 4) {
        float4 v = *(float4*)&buf[i];
        v.x *= inv; v.y *= inv; v.z *= inv; v.w *= inv;
        uint32_t h[2], l[2];
        h[0] = pack_hi(v.x, v.y, l[0]);
        h[1] = pack_hi(v.z, v.w, l[1]);
        *(uint2*)(prow + i)       = *(uint2*)h;
        *(uint2*)(prow + SEQ + i) = *(uint2*)l;
    }
}

// ===========================================================================
// Launch
// ===========================================================================
extern "C" void kernel_launch(void* const* d_in, const int* in_sizes, int n_in,
                              void* d_out, int out_size)
{
    const float* X    = (const float*)d_in[0];
    const float* mask = (const float*)d_in[1];
    const float* Wq   = (const float*)d_in[2];
    const float* bq   = (const float*)d_in[3];
    const float* Wk   = (const float*)d_in[4];
    const float* bk   = (const float*)d_in[5];
    const float* Wv   = (const float*)d_in[6];
    const float* bv   = (const float*)d_in[7];
    float* out = (float*)d_out;

    cudaFuncSetAttribute(gemm_hmma, cudaFuncAttributeMaxDynamicSharedMemorySize,
                         GEMM_SMEM);

    // 1) hi/lo converts of inputs (vectorized, 8 elem/thread)
    {
        const size_t nX = (size_t)MROWS * HID;
        const size_t nW = (size_t)HID * HID;
        cvt_hilo8<<<(unsigned)(nX / 8 / 256), 256>>>(X,  SEL_XHL, HID, nX);
        cvt_hilo8<<<(unsigned)(nW / 8 / 256), 256>>>(Wq, SEL_WQ,  HID, nW);
        cvt_hilo8<<<(unsigned)(nW / 8 / 256), 256>>>(Wk, SEL_WK,  HID, nW);
        cvt_hilo8<<<(unsigned)(nW / 8 / 256), 256>>>(Wv, SEL_WV,  HID, nW);
    }

    // 2) QKV projections. Q,K: fused bf16 hi/lo epilogue.
    //    V: fused TRANSPOSED bf16 hi/lo epilogue straight into g_Vthl.
    {
        dim3 g(HID / 128, MROWS / 128, 1);
        gemm_hmma<<<g, 256, GEMM_SMEM>>>(SEL_XHL, SEL_WQ, bq, 1, SEL_QHL, nullptr,
                                         nullptr, 0.f, HID, HID, 0, 0, 0);
        gemm_hmma<<<g, 256, GEMM_SMEM>>>(SEL_XHL, SEL_WK, bk, 1, SEL_KHL, nullptr,
                                         nullptr, 0.f, HID, HID, 0, 0, 0);
        gemm_hmma<<<g, 256, GEMM_SMEM>>>(SEL_XHL, SEL_WV, bv, 3, SEL_VTHL, nullptr,
                                         nullptr, 0.f, HID, HID, 0, 0, 0);
    }

    // 3) Scores = (Q @ K^T) * scale + mask  (fused epilogue) -> g_Sf
    {
        dim3 g(SEQ / 128, SEQ / 128, BATCH);
        gemm_hmma<<<g, 256, GEMM_SMEM>>>(SEL_QHL, SEL_KHL, nullptr, 2, FSEL_SF, nullptr,
                                         mask, 0.08838834764831845f,
                                         HID, SEQ,
                                         (size_t)SEQ * KX, (size_t)SEQ * KX,
                                         (size_t)SEQ * SEQ);
    }

    // 4) Softmax -> g_Phl (bf16 hi/lo)
    softmax_rows<<<MROWS, 256>>>();

    // 5) Context = P @ Vt^T per batch -> d_out
    {
        dim3 g(HID / 128, SEQ / 128, BATCH);
        gemm_hmma<<<g, 256, GEMM_SMEM>>>(SEL_PHL, SEL_VTHL, nullptr, 0, -1, out,
                                         nullptr, 0.f, SEQ, HID,
                                         (size_t)SEQ * KPV, (size_t)HID * KPV,
                                         (size_t)SEQ * HID);
    }
}